// round 16
// baseline (speedup 1.0000x reference)
#include <cuda_runtime.h>
#include <cuda_bf16.h>
#include <cstdint>

// ============================================================================
// BinaryToCost: out[i] = x_i @ Q @ x_i  (x: 1024x2048 {0,1} fp32, Q: 2048^2 fp32)
// x binary (x^2=x)  =>  x^T Q x = x^T U x, U upper-triangular folded:
//   B[n][j] = (j<n ? Q_jn + Q_nj : (j==n ? Q_nn : 0))  -> 44% fewer MACs.
// Split-precision bf16 (U = Uhi + Ulo), z-split over 2 passes, flat 16-unit
// per-CTA triangular schedule (144 CTAs = one wave), smem schedule table,
// vectorized prep (single-pass x: bf16 pack + byte-wise bitmask emission),
// bit-packed x-mask folds, last-CTA final reduction.
// ============================================================================

#define NDIM 2048
#define BDIM 1024
#define BM 128
#define BN 256
#define BK 64
#define NUNITS 144             // sum of 4*(t+1), t=0..7
#define NSLICE 9
#define UPC (NUNITS / NSLICE)  // 16 units per CTA
#define MT (BDIM / BM)         // 8
#define NCTA (NSLICE * MT * 2) // 144
#define NSTAGE 4
#define A_BYTES 16384
#define B_BYTES 32768
#define STAGE_BYTES (A_BYTES + B_BYTES)
#define SMEM_BYTES (NSTAGE * STAGE_BYTES)  // 192 KB

// ---------------------------------------------------------------------------
__device__ __align__(16) __nv_bfloat16 g_xh[BDIM * NDIM];   // bf16(x) [m][k]
__device__ __align__(16) __nv_bfloat16 g_uhi[NDIM * NDIM];  // B[n][j] hi
__device__ __align__(16) __nv_bfloat16 g_ulo[NDIM * NDIM];  // B[n][j] lo
__device__ __align__(16) unsigned long long g_xbits[BDIM * 32]; // [m][n/64]
__device__ float g_partial[2 * NSLICE * BDIM];              // [z*9+slice][m]
__device__ unsigned g_cnt = 0;

// ---------------------------------------------------------------------------
__device__ __forceinline__ uint32_t smem_u32(const void* p) {
    return (uint32_t)__cvta_generic_to_shared(p);
}
__device__ __forceinline__ uint32_t sw128(uint32_t off) {
    return off ^ ((off >> 3) & 0x70);
}
__device__ __forceinline__ void cp_async16(uint32_t dst, const void* src) {
    asm volatile("cp.async.cg.shared.global [%0], [%1], 16;"
                 :: "r"(dst), "l"(src) : "memory");
}

#define LDSM_X4(r, addr)                                                      \
    asm volatile("ldmatrix.sync.aligned.m8n8.x4.shared.b16 {%0,%1,%2,%3}, [%4];" \
                 : "=r"((r)[0]), "=r"((r)[1]), "=r"((r)[2]), "=r"((r)[3])     \
                 : "r"(addr))

__device__ __forceinline__ void mma16816(float* d, const uint32_t* a,
                                         const uint32_t* b) {
    asm volatile(
        "mma.sync.aligned.m16n8k16.row.col.f32.bf16.bf16.f32 "
        "{%0,%1,%2,%3}, {%4,%5,%6,%7}, {%8,%9}, {%0,%1,%2,%3};"
        : "+f"(d[0]), "+f"(d[1]), "+f"(d[2]), "+f"(d[3])
        : "r"(a[0]), "r"(a[1]), "r"(a[2]), "r"(a[3]), "r"(b[0]), "r"(b[1]));
}

// unit u (0..143) -> (t, c): largest t with 2t(t+1) <= u (integer-clamped).
__device__ __forceinline__ void unit_tc(int u, int& t, int& c) {
    int tt = (int)((__fsqrt_rn(2.0f * (float)u + 1.0f) - 1.0f) * 0.5f);
    while (2 * (tt + 1) * (tt + 2) <= u) ++tt;
    while (2 * tt * (tt + 1) > u) --tt;
    t = tt;
    c = u - 2 * tt * (tt + 1);
}

// ---------------------------------------------------------------------------
// Prep: b<4096: build U 32x32 block (vectorized 8B stores);
//       else: pack x bf16 AND emit byte-wise x bitmask (single x read).
// ---------------------------------------------------------------------------
__global__ void __launch_bounds__(256)
k_prep(const float* __restrict__ x, const float* __restrict__ Q) {
    const int b = blockIdx.x;
    if (b < 4096) {
        const int nb = b >> 6, jb = b & 63;
        if (jb >= 8 * (nb / 8 + 1)) return;  // never read by any tile
        const int n0 = nb * 32, j0 = jb * 32;
        const int row = threadIdx.x >> 3;   // 0..31
        const int qc = threadIdx.x & 7;     // 4-col group 0..7

        if (jb > nb) {  // diagonal-padding zero block: one 8B store per array
            uint2 z = make_uint2(0u, 0u);
            *reinterpret_cast<uint2*>(g_uhi + (n0 + row) * NDIM + j0 + 4 * qc) = z;
            *reinterpret_cast<uint2*>(g_ulo + (n0 + row) * NDIM + j0 + 4 * qc) = z;
            return;
        }

        __shared__ float S[32][33];
        {
            const int tx = threadIdx.x & 31, ty = threadIdx.x >> 5;
#pragma unroll
            for (int r = 0; r < 4; ++r)  // S[a][b] = Q[j0+a][n0+b]
                S[ty + 8 * r][tx] = Q[(j0 + ty + 8 * r) * NDIM + n0 + tx];
        }
        __syncthreads();

        const int n = n0 + row;
        float4 D4 = *reinterpret_cast<const float4*>(Q + n * NDIM + j0 + 4 * qc);
        float Dv[4] = {D4.x, D4.y, D4.z, D4.w};
        __nv_bfloat16 h[4], l[4];
#pragma unroll
        for (int e = 0; e < 4; ++e) {
            int j = j0 + 4 * qc + e;
            float T = S[4 * qc + e][row];  // Q_jn
            float u = (j < n) ? (Dv[e] + T) : ((j == n) ? Dv[e] : 0.0f);
            h[e] = __float2bfloat16(u);
            l[e] = __float2bfloat16(u - __bfloat162float(h[e]));
        }
        *reinterpret_cast<uint2*>(g_uhi + n * NDIM + j0 + 4 * qc) =
            *reinterpret_cast<uint2*>(h);
        *reinterpret_cast<uint2*>(g_ulo + n * NDIM + j0 + 4 * qc) =
            *reinterpret_cast<uint2*>(l);
    } else {
        // x: one read -> bf16 pack + bitmask byte.
        // group i covers x elements [8i, 8i+8): row m = i>>8, cols (i&255)*8...
        int i = (b - 4096) * 256 + threadIdx.x;
        const float4* x4 = reinterpret_cast<const float4*>(x) + i * 2;
        float4 v0 = x4[0], v1 = x4[1];
        __nv_bfloat162 p[4];
        p[0] = __floats2bfloat162_rn(v0.x, v0.y);
        p[1] = __floats2bfloat162_rn(v0.z, v0.w);
        p[2] = __floats2bfloat162_rn(v1.x, v1.y);
        p[3] = __floats2bfloat162_rn(v1.z, v1.w);
        reinterpret_cast<uint4*>(g_xh)[i] = *reinterpret_cast<uint4*>(p);

        unsigned msk = (v0.x != 0.0f) | ((v0.y != 0.0f) << 1) |
                       ((v0.z != 0.0f) << 2) | ((v0.w != 0.0f) << 3) |
                       ((v1.x != 0.0f) << 4) | ((v1.y != 0.0f) << 5) |
                       ((v1.z != 0.0f) << 6) | ((v1.w != 0.0f) << 7);
        // byte k of little-endian word w covers elements 64w+8k..+7  ✓
        reinterpret_cast<uint8_t*>(g_xbits)[(i >> 8) * 256 + (i & 255)] =
            (uint8_t)msk;
    }
}

// ---------------------------------------------------------------------------
// GEMM: grid (NSLICE, MT, 2). 256 threads, 8 warps (2M x 4N), warp 64x64.
// smem schedule table; folds at precomputed n-tile boundaries.
// ---------------------------------------------------------------------------
__global__ void __launch_bounds__(256, 1)
k_gemm(float* __restrict__ out) {
    extern __shared__ __align__(1024) uint8_t smem[];
    __shared__ uint32_t s_sched[UPC];  // (t<<8) | c | (boundary<<15)
    __shared__ unsigned s_old;

    const int tid = threadIdx.x;
    const int wid = tid >> 5;
    const int lane = tid & 31;
    const int slice = blockIdx.x;
    const int m0 = blockIdx.y * BM;
    const int wm = (wid >> 2) * 64;
    const int wn = (wid & 3) * 64;
    const int grp = lane >> 3;
    const int ri = lane & 7;
    const int g4 = lane >> 2;
    const int tc2 = (lane & 3) * 2;
    const __nv_bfloat16* __restrict__ us = blockIdx.z ? g_ulo : g_uhi;
    const int ubase = slice * UPC;

    if (tid < UPC) {
        int t, c;
        unit_tc(ubase + tid, t, c);
        uint32_t e = (uint32_t)(t << 8) | (uint32_t)c;
        if (tid == UPC - 1 || c == 4 * t + 3) e |= 1u << 15;
        s_sched[tid] = e;
    }
    __syncthreads();

    auto stage_load = [&](int i) {
        const uint32_t e = s_sched[i];
        const int n0u = (int)((e >> 8) & 0x7f) * BN;
        const int kbE = (int)(e & 0x7f) * BK;
        uint32_t sa = smem_u32(smem) + (i % NSTAGE) * STAGE_BYTES;
        uint32_t sb = sa + A_BYTES;
#pragma unroll
        for (int q = 0; q < 4; ++q) {  // A: 128 rows
            int g = tid + 256 * q;
            int rr = g >> 3, cc = g & 7;
            uint32_t off = sw128((uint32_t)(rr * 128 + cc * 16));
            cp_async16(sa + off, g_xh + (m0 + rr) * NDIM + kbE + cc * 8);
        }
#pragma unroll
        for (int q = 0; q < 8; ++q) {  // B: 256 rows
            int g = tid + 256 * q;
            int rr = g >> 3, cc = g & 7;
            uint32_t off = sw128((uint32_t)(rr * 128 + cc * 16));
            cp_async16(sb + off, us + (n0u + rr) * NDIM + kbE + cc * 8);
        }
        asm volatile("cp.async.commit_group;" ::: "memory");
    };

    float cfrag[4][8][4];
#pragma unroll
    for (int mt = 0; mt < 4; ++mt)
#pragma unroll
        for (int nt = 0; nt < 8; ++nt)
#pragma unroll
            for (int r = 0; r < 4; ++r) cfrag[mt][nt][r] = 0.0f;

    float facc0[4] = {0, 0, 0, 0}, facc1[4] = {0, 0, 0, 0};

    stage_load(0);
    stage_load(1);
    stage_load(2);

    for (int i = 0; i < UPC; ++i) {
        if (i < UPC - 2)
            asm volatile("cp.async.wait_group 2;" ::: "memory");
        else if (i == UPC - 2)
            asm volatile("cp.async.wait_group 1;" ::: "memory");
        else
            asm volatile("cp.async.wait_group 0;" ::: "memory");
        __syncthreads();

        if (i + 3 < UPC) stage_load(i + 3);

        const uint32_t sa = smem_u32(smem) + (i % NSTAGE) * STAGE_BYTES;
        const uint32_t sb = sa + A_BYTES;

#pragma unroll
        for (int s = 0; s < 4; ++s) {
            const int kb = s * 32;
            uint32_t a[4][4];
#pragma unroll
            for (int mt = 0; mt < 4; ++mt) {
                int row = wm + mt * 16 + (grp & 1) * 8 + ri;
                uint32_t addr = sa + sw128((uint32_t)(row * 128 + kb + (grp >> 1) * 16));
                LDSM_X4(a[mt], addr);
            }
            uint32_t b[4][4];
#pragma unroll
            for (int nt2 = 0; nt2 < 4; ++nt2) {
                int row = wn + nt2 * 16 + (grp >> 1) * 8 + ri;
                uint32_t addr = sb + sw128((uint32_t)(row * 128 + kb + (grp & 1) * 16));
                LDSM_X4(b[nt2], addr);
            }
#pragma unroll
            for (int mt = 0; mt < 4; ++mt)
#pragma unroll
                for (int nt = 0; nt < 8; ++nt)
                    mma16816(cfrag[mt][nt], a[mt], &b[nt >> 1][(nt & 1) * 2]);
        }

        // Fold at n-tile boundary / schedule end (flag precomputed).
        const uint32_t e = s_sched[i];
        if (e & (1u << 15)) {
            const int t = (int)((e >> 8) & 0x7f);
            const int nw = (t * BN + wn) >> 6;  // uint64 word per warp n-band
#pragma unroll
            for (int mt = 0; mt < 4; ++mt) {
                const int r0 = m0 + wm + mt * 16 + g4;
                const unsigned long long w0 = g_xbits[r0 * 32 + nw];
                const unsigned long long w1 = g_xbits[(r0 + 8) * 32 + nw];
                float a0 = 0.0f, a1 = 0.0f;
#pragma unroll
                for (int nt = 0; nt < 8; ++nt) {
                    const int bp = nt * 8 + tc2;
                    if ((w0 >> bp) & 1)       a0 += cfrag[mt][nt][0];
                    if ((w0 >> (bp + 1)) & 1) a0 += cfrag[mt][nt][1];
                    if ((w1 >> bp) & 1)       a1 += cfrag[mt][nt][2];
                    if ((w1 >> (bp + 1)) & 1) a1 += cfrag[mt][nt][3];
#pragma unroll
                    for (int r = 0; r < 4; ++r) cfrag[mt][nt][r] = 0.0f;
                }
                facc0[mt] += a0;
                facc1[mt] += a1;
            }
        }
    }

    // ---- Final per-CTA reduce (deterministic) ----
#pragma unroll
    for (int mt = 0; mt < 4; ++mt) {
#pragma unroll
        for (int o = 1; o <= 2; o <<= 1) {
            facc0[mt] += __shfl_xor_sync(0xFFFFFFFF, facc0[mt], o);
            facc1[mt] += __shfl_xor_sync(0xFFFFFFFF, facc1[mt], o);
        }
    }
    __syncthreads();  // stage smem free
    float* red = reinterpret_cast<float*>(smem);  // [4 n-groups][128 rows]
    if ((lane & 3) == 0) {
        const int ng = wid & 3;
#pragma unroll
        for (int mt = 0; mt < 4; ++mt) {
            int row = wm + mt * 16 + g4;
            red[ng * 128 + row] = facc0[mt];
            red[ng * 128 + row + 8] = facc1[mt];
        }
    }
    __syncthreads();
    if (tid < 128) {
        float p = red[tid] + red[128 + tid] + red[256 + tid] + red[384 + tid];
        g_partial[(blockIdx.z * NSLICE + slice) * BDIM + m0 + tid] = p;
    }

    // ---- Last-CTA final reduction ----
    __syncthreads();
    if (tid == 0) {
        __threadfence();
        s_old = atomicAdd(&g_cnt, 1u);
    }
    __syncthreads();
    if (s_old == NCTA - 1) {
        __threadfence();
        for (int m = tid; m < BDIM; m += 256) {
            float s = 0.0f;
#pragma unroll
            for (int p = 0; p < 2 * NSLICE; ++p) s += g_partial[p * BDIM + m];
            out[m] = s;
        }
        if (tid == 0) g_cnt = 0;  // reset for next graph replay
    }
}

// ---------------------------------------------------------------------------
extern "C" void kernel_launch(void* const* d_in, const int* in_sizes, int n_in,
                              void* d_out, int out_size) {
    const float* x = (const float*)d_in[0];  // [1024, 2048]
    const float* Q = (const float*)d_in[1];  // [2048, 2048]
    float* out = (float*)d_out;              // [1024]

    static bool attr_set = false;
    if (!attr_set) {
        cudaFuncSetAttribute(k_gemm, cudaFuncAttributeMaxDynamicSharedMemorySize,
                             SMEM_BYTES);
        attr_set = true;
    }

    k_prep<<<4096 + 1024, 256>>>(x, Q);
    k_gemm<<<dim3(NSLICE, MT, 2), 256, SMEM_BYTES>>>(out);
}

// round 17
// speedup vs baseline: 1.5561x; 1.5561x over previous
#include <cuda_runtime.h>
#include <cuda_bf16.h>
#include <cstdint>

// ============================================================================
// BinaryToCost: out[i] = x_i @ Q @ x_i  (x: 1024x2048 {0,1} fp32, Q: 2048^2 fp32)
// x binary (x^2=x)  =>  x^T Q x = x^T U x, U upper-triangular folded:
//   B[n][j] = (j<n ? Q_jn + Q_nj : (j==n ? Q_nn : 0))  -> 44% fewer MACs.
// Split-precision bf16 (U = Uhi + Ulo), z-split over 2 passes, flat 16-unit
// per-CTA triangular schedule (144 CTAs = one wave), smem schedule table,
// single-pass x prep (bf16 pack + byte-wise bitmask), bit-packed folds,
// vectorized last-CTA final reduction.
// ============================================================================

#define NDIM 2048
#define BDIM 1024
#define BM 128
#define BN 256
#define BK 64
#define NUNITS 144             // sum of 4*(t+1), t=0..7
#define NSLICE 9
#define UPC (NUNITS / NSLICE)  // 16 units per CTA
#define MT (BDIM / BM)         // 8
#define NCTA (NSLICE * MT * 2) // 144
#define NSTAGE 4
#define A_BYTES 16384
#define B_BYTES 32768
#define STAGE_BYTES (A_BYTES + B_BYTES)
#define SMEM_BYTES (NSTAGE * STAGE_BYTES)  // 192 KB

// ---------------------------------------------------------------------------
__device__ __align__(16) __nv_bfloat16 g_xh[BDIM * NDIM];   // bf16(x) [m][k]
__device__ __align__(16) __nv_bfloat16 g_uhi[NDIM * NDIM];  // B[n][j] hi
__device__ __align__(16) __nv_bfloat16 g_ulo[NDIM * NDIM];  // B[n][j] lo
__device__ __align__(16) unsigned long long g_xbits[BDIM * 32]; // [m][n/64]
__device__ __align__(16) float g_partial[2 * NSLICE * BDIM];   // [z*9+s][m]
__device__ unsigned g_cnt = 0;

// ---------------------------------------------------------------------------
__device__ __forceinline__ uint32_t smem_u32(const void* p) {
    return (uint32_t)__cvta_generic_to_shared(p);
}
__device__ __forceinline__ uint32_t sw128(uint32_t off) {
    return off ^ ((off >> 3) & 0x70);
}
__device__ __forceinline__ void cp_async16(uint32_t dst, const void* src) {
    asm volatile("cp.async.cg.shared.global [%0], [%1], 16;"
                 :: "r"(dst), "l"(src) : "memory");
}

#define LDSM_X4(r, addr)                                                      \
    asm volatile("ldmatrix.sync.aligned.m8n8.x4.shared.b16 {%0,%1,%2,%3}, [%4];" \
                 : "=r"((r)[0]), "=r"((r)[1]), "=r"((r)[2]), "=r"((r)[3])     \
                 : "r"(addr))

__device__ __forceinline__ void mma16816(float* d, const uint32_t* a,
                                         const uint32_t* b) {
    asm volatile(
        "mma.sync.aligned.m16n8k16.row.col.f32.bf16.bf16.f32 "
        "{%0,%1,%2,%3}, {%4,%5,%6,%7}, {%8,%9}, {%0,%1,%2,%3};"
        : "+f"(d[0]), "+f"(d[1]), "+f"(d[2]), "+f"(d[3])
        : "r"(a[0]), "r"(a[1]), "r"(a[2]), "r"(a[3]), "r"(b[0]), "r"(b[1]));
}

// unit u (0..143) -> (t, c): largest t with 2t(t+1) <= u (integer-clamped).
__device__ __forceinline__ void unit_tc(int u, int& t, int& c) {
    int tt = (int)((__fsqrt_rn(2.0f * (float)u + 1.0f) - 1.0f) * 0.5f);
    while (2 * (tt + 1) * (tt + 2) <= u) ++tt;
    while (2 * tt * (tt + 1) > u) --tt;
    t = tt;
    c = u - 2 * tt * (tt + 1);
}

// ---------------------------------------------------------------------------
// Prep: b<4096: build U 32x32 block (vectorized 8B stores);
//       else: pack x bf16 AND emit byte-wise x bitmask (single x read).
// ---------------------------------------------------------------------------
__global__ void __launch_bounds__(256)
k_prep(const float* __restrict__ x, const float* __restrict__ Q) {
    const int b = blockIdx.x;
    if (b < 4096) {
        const int nb = b >> 6, jb = b & 63;
        if (jb >= 8 * (nb / 8 + 1)) return;  // never read by any tile
        const int n0 = nb * 32, j0 = jb * 32;
        const int row = threadIdx.x >> 3;   // 0..31
        const int qc = threadIdx.x & 7;     // 4-col group 0..7

        if (jb > nb) {  // diagonal-padding zero block: one 8B store per array
            uint2 z = make_uint2(0u, 0u);
            *reinterpret_cast<uint2*>(g_uhi + (n0 + row) * NDIM + j0 + 4 * qc) = z;
            *reinterpret_cast<uint2*>(g_ulo + (n0 + row) * NDIM + j0 + 4 * qc) = z;
            return;
        }

        __shared__ float S[32][33];
        {
            const int tx = threadIdx.x & 31, ty = threadIdx.x >> 5;
#pragma unroll
            for (int r = 0; r < 4; ++r)  // S[a][b] = Q[j0+a][n0+b]
                S[ty + 8 * r][tx] = Q[(j0 + ty + 8 * r) * NDIM + n0 + tx];
        }
        __syncthreads();

        const int n = n0 + row;
        float4 D4 = *reinterpret_cast<const float4*>(Q + n * NDIM + j0 + 4 * qc);
        float Dv[4] = {D4.x, D4.y, D4.z, D4.w};
        __nv_bfloat16 h[4], l[4];
#pragma unroll
        for (int e = 0; e < 4; ++e) {
            int j = j0 + 4 * qc + e;
            float T = S[4 * qc + e][row];  // Q_jn
            float u = (j < n) ? (Dv[e] + T) : ((j == n) ? Dv[e] : 0.0f);
            h[e] = __float2bfloat16(u);
            l[e] = __float2bfloat16(u - __bfloat162float(h[e]));
        }
        *reinterpret_cast<uint2*>(g_uhi + n * NDIM + j0 + 4 * qc) =
            *reinterpret_cast<uint2*>(h);
        *reinterpret_cast<uint2*>(g_ulo + n * NDIM + j0 + 4 * qc) =
            *reinterpret_cast<uint2*>(l);
    } else {
        // x: one read -> bf16 pack + bitmask byte.
        int i = (b - 4096) * 256 + threadIdx.x;  // 8-elem group over x
        const float4* x4 = reinterpret_cast<const float4*>(x) + i * 2;
        float4 v0 = x4[0], v1 = x4[1];
        __nv_bfloat162 p[4];
        p[0] = __floats2bfloat162_rn(v0.x, v0.y);
        p[1] = __floats2bfloat162_rn(v0.z, v0.w);
        p[2] = __floats2bfloat162_rn(v1.x, v1.y);
        p[3] = __floats2bfloat162_rn(v1.z, v1.w);
        reinterpret_cast<uint4*>(g_xh)[i] = *reinterpret_cast<uint4*>(p);

        unsigned msk = (v0.x != 0.0f) | ((v0.y != 0.0f) << 1) |
                       ((v0.z != 0.0f) << 2) | ((v0.w != 0.0f) << 3) |
                       ((v1.x != 0.0f) << 4) | ((v1.y != 0.0f) << 5) |
                       ((v1.z != 0.0f) << 6) | ((v1.w != 0.0f) << 7);
        // byte k of little-endian word w covers elements 64w+8k..+7
        reinterpret_cast<uint8_t*>(g_xbits)[(i >> 8) * 256 + (i & 255)] =
            (uint8_t)msk;
    }
}

// ---------------------------------------------------------------------------
// GEMM: grid (NSLICE, MT, 2). 256 threads, 8 warps (2M x 4N), warp 64x64.
// smem schedule table; folds at precomputed n-tile boundaries.
// ---------------------------------------------------------------------------
__global__ void __launch_bounds__(256, 1)
k_gemm(float* __restrict__ out) {
    extern __shared__ __align__(1024) uint8_t smem[];
    __shared__ uint32_t s_sched[UPC];  // (t<<8) | c | (boundary<<15)
    __shared__ unsigned s_old;

    const int tid = threadIdx.x;
    const int wid = tid >> 5;
    const int lane = tid & 31;
    const int slice = blockIdx.x;
    const int m0 = blockIdx.y * BM;
    const int wm = (wid >> 2) * 64;
    const int wn = (wid & 3) * 64;
    const int grp = lane >> 3;
    const int ri = lane & 7;
    const int g4 = lane >> 2;
    const int tc2 = (lane & 3) * 2;
    const __nv_bfloat16* __restrict__ us = blockIdx.z ? g_ulo : g_uhi;
    const int ubase = slice * UPC;

    if (tid < UPC) {
        int t, c;
        unit_tc(ubase + tid, t, c);
        uint32_t e = (uint32_t)(t << 8) | (uint32_t)c;
        if (tid == UPC - 1 || c == 4 * t + 3) e |= 1u << 15;
        s_sched[tid] = e;
    }
    __syncthreads();

    auto stage_load = [&](int i) {
        const uint32_t e = s_sched[i];
        const int n0u = (int)((e >> 8) & 0x7f) * BN;
        const int kbE = (int)(e & 0x7f) * BK;
        uint32_t sa = smem_u32(smem) + (i % NSTAGE) * STAGE_BYTES;
        uint32_t sb = sa + A_BYTES;
#pragma unroll
        for (int q = 0; q < 4; ++q) {  // A: 128 rows
            int g = tid + 256 * q;
            int rr = g >> 3, cc = g & 7;
            uint32_t off = sw128((uint32_t)(rr * 128 + cc * 16));
            cp_async16(sa + off, g_xh + (m0 + rr) * NDIM + kbE + cc * 8);
        }
#pragma unroll
        for (int q = 0; q < 8; ++q) {  // B: 256 rows
            int g = tid + 256 * q;
            int rr = g >> 3, cc = g & 7;
            uint32_t off = sw128((uint32_t)(rr * 128 + cc * 16));
            cp_async16(sb + off, us + (n0u + rr) * NDIM + kbE + cc * 8);
        }
        asm volatile("cp.async.commit_group;" ::: "memory");
    };

    float cfrag[4][8][4];
#pragma unroll
    for (int mt = 0; mt < 4; ++mt)
#pragma unroll
        for (int nt = 0; nt < 8; ++nt)
#pragma unroll
            for (int r = 0; r < 4; ++r) cfrag[mt][nt][r] = 0.0f;

    float facc0[4] = {0, 0, 0, 0}, facc1[4] = {0, 0, 0, 0};

    stage_load(0);
    stage_load(1);
    stage_load(2);

    for (int i = 0; i < UPC; ++i) {
        if (i < UPC - 2)
            asm volatile("cp.async.wait_group 2;" ::: "memory");
        else if (i == UPC - 2)
            asm volatile("cp.async.wait_group 1;" ::: "memory");
        else
            asm volatile("cp.async.wait_group 0;" ::: "memory");
        __syncthreads();

        if (i + 3 < UPC) stage_load(i + 3);

        const uint32_t sa = smem_u32(smem) + (i % NSTAGE) * STAGE_BYTES;
        const uint32_t sb = sa + A_BYTES;

#pragma unroll
        for (int s = 0; s < 4; ++s) {
            const int kb = s * 32;
            uint32_t a[4][4];
#pragma unroll
            for (int mt = 0; mt < 4; ++mt) {
                int row = wm + mt * 16 + (grp & 1) * 8 + ri;
                uint32_t addr = sa + sw128((uint32_t)(row * 128 + kb + (grp >> 1) * 16));
                LDSM_X4(a[mt], addr);
            }
            uint32_t b[4][4];
#pragma unroll
            for (int nt2 = 0; nt2 < 4; ++nt2) {
                int row = wn + nt2 * 16 + (grp >> 1) * 8 + ri;
                uint32_t addr = sb + sw128((uint32_t)(row * 128 + kb + (grp & 1) * 16));
                LDSM_X4(b[nt2], addr);
            }
#pragma unroll
            for (int mt = 0; mt < 4; ++mt)
#pragma unroll
                for (int nt = 0; nt < 8; ++nt)
                    mma16816(cfrag[mt][nt], a[mt], &b[nt >> 1][(nt & 1) * 2]);
        }

        // Fold at n-tile boundary / schedule end (flag precomputed).
        const uint32_t e = s_sched[i];
        if (e & (1u << 15)) {
            const int t = (int)((e >> 8) & 0x7f);
            const int nw = (t * BN + wn) >> 6;  // uint64 word per warp n-band
#pragma unroll
            for (int mt = 0; mt < 4; ++mt) {
                const int r0 = m0 + wm + mt * 16 + g4;
                const unsigned long long w0 = g_xbits[r0 * 32 + nw];
                const unsigned long long w1 = g_xbits[(r0 + 8) * 32 + nw];
                float a0 = 0.0f, a1 = 0.0f;
#pragma unroll
                for (int nt = 0; nt < 8; ++nt) {
                    const int bp = nt * 8 + tc2;
                    if ((w0 >> bp) & 1)       a0 += cfrag[mt][nt][0];
                    if ((w0 >> (bp + 1)) & 1) a0 += cfrag[mt][nt][1];
                    if ((w1 >> bp) & 1)       a1 += cfrag[mt][nt][2];
                    if ((w1 >> (bp + 1)) & 1) a1 += cfrag[mt][nt][3];
#pragma unroll
                    for (int r = 0; r < 4; ++r) cfrag[mt][nt][r] = 0.0f;
                }
                facc0[mt] += a0;
                facc1[mt] += a1;
            }
        }
    }

    // ---- Final per-CTA reduce (deterministic) ----
#pragma unroll
    for (int mt = 0; mt < 4; ++mt) {
#pragma unroll
        for (int o = 1; o <= 2; o <<= 1) {
            facc0[mt] += __shfl_xor_sync(0xFFFFFFFF, facc0[mt], o);
            facc1[mt] += __shfl_xor_sync(0xFFFFFFFF, facc1[mt], o);
        }
    }
    __syncthreads();  // stage smem free
    float* red = reinterpret_cast<float*>(smem);  // [4 n-groups][128 rows]
    if ((lane & 3) == 0) {
        const int ng = wid & 3;
#pragma unroll
        for (int mt = 0; mt < 4; ++mt) {
            int row = wm + mt * 16 + g4;
            red[ng * 128 + row] = facc0[mt];
            red[ng * 128 + row + 8] = facc1[mt];
        }
    }
    __syncthreads();
    if (tid < 128) {
        float p = red[tid] + red[128 + tid] + red[256 + tid] + red[384 + tid];
        g_partial[(blockIdx.z * NSLICE + slice) * BDIM + m0 + tid] = p;
    }

    // ---- Last-CTA final reduction (vectorized: 4 m-rows per thread) ----
    __syncthreads();
    if (tid == 0) {
        __threadfence();
        s_old = atomicAdd(&g_cnt, 1u);
    }
    __syncthreads();
    if (s_old == NCTA - 1) {
        __threadfence();
        int m4 = tid * 4;  // 256 threads x 4 rows = 1024
        float4 s = make_float4(0.f, 0.f, 0.f, 0.f);
#pragma unroll
        for (int p = 0; p < 2 * NSLICE; ++p) {
            float4 v = *reinterpret_cast<const float4*>(g_partial + p * BDIM + m4);
            s.x += v.x; s.y += v.y; s.z += v.z; s.w += v.w;
        }
        *reinterpret_cast<float4*>(out + m4) = s;
        if (tid == 0) g_cnt = 0;  // reset for next graph replay
    }
}

// ---------------------------------------------------------------------------
extern "C" void kernel_launch(void* const* d_in, const int* in_sizes, int n_in,
                              void* d_out, int out_size) {
    const float* x = (const float*)d_in[0];  // [1024, 2048]
    const float* Q = (const float*)d_in[1];  // [2048, 2048]
    float* out = (float*)d_out;              // [1024]

    static bool attr_set = false;
    if (!attr_set) {
        cudaFuncSetAttribute(k_gemm, cudaFuncAttributeMaxDynamicSharedMemorySize,
                             SMEM_BYTES);
        attr_set = true;
    }

    k_prep<<<4096 + 1024, 256>>>(x, Q);
    k_gemm<<<dim3(NSLICE, MT, 2), 256, SMEM_BYTES>>>(out);
}